// round 16
// baseline (speedup 1.0000x reference)
#include <cuda_runtime.h>
#include <cuda_fp16.h>
#include <cstdint>

#define B_ 32768
#define D_ 768
#define H_ 1024
#define L_ 256

// ---------------- GEMM tiling ----------------
#define TM 128
#define TN 128
#define NTHREAD 256
#define AT_BYTES (128 * 128)              // A tile: 128 rows x 128B
#define WT_BYTES (128 * 128)              // W tile: 128 rows x 128B
#define STG_BYTES (AT_BYTES + WT_BYTES)   // 32768
#define NSTAGE 3
#define SM_TOTAL (NSTAGE * STG_BYTES)     // 98304 -> 2 CTAs/SM

// ---------------- scratch ----------------
static __device__ float  g_f32[(size_t)B_ * 2048];   // aliased as half buffer A
static __device__ __half g_h0[(size_t)B_ * 2048];    // half buffer B
static __device__ __half g_h1[(size_t)B_ * 256];     // z_enh
static __device__ __half g_cvt[32505856];            // x + weights, fp16

// offsets into g_cvt (halfs)
#define OFF_X    0
#define OFF_EW1  25165824
#define OFF_EW2  25952256
#define OFF_MUW  27000832
#define OFF_LVW  27262976
#define OFF_DIW  27525120
#define OFF_DW1  27787264
#define OFF_DW2  28835840
#define OFF_DW3  30932992

// ---------------- helpers ----------------
__device__ __forceinline__ uint32_t smem_u32(const void* p) {
    uint32_t a;
    asm("{ .reg .u64 t; cvta.to.shared.u64 t, %1; cvt.u32.u64 %0, t; }" : "=r"(a) : "l"(p));
    return a;
}
__device__ __forceinline__ void cp16(uint32_t sa, const void* g) {
    asm volatile("cp.async.cg.shared.global [%0], [%1], 16;" :: "r"(sa), "l"(g));
}
__device__ __forceinline__ void mma16(float* c, uint32_t a0, uint32_t a1, uint32_t a2, uint32_t a3,
                                      uint32_t b0, uint32_t b1) {
    asm volatile("mma.sync.aligned.m16n8k16.row.col.f32.f16.f16.f32 "
                 "{%0,%1,%2,%3}, {%4,%5,%6,%7}, {%8,%9}, {%0,%1,%2,%3};"
                 : "+f"(c[0]), "+f"(c[1]), "+f"(c[2]), "+f"(c[3])
                 : "r"(a0), "r"(a1), "r"(a2), "r"(a3), "r"(b0), "r"(b1));
}
__device__ __forceinline__ void ldm4(uint32_t* r, uint32_t addr) {
    asm volatile("ldmatrix.sync.aligned.m8n8.x4.shared.b16 {%0,%1,%2,%3}, [%4];"
                 : "=r"(r[0]), "=r"(r[1]), "=r"(r[2]), "=r"(r[3]) : "r"(addr));
}

// ===================================================================
// conv_all: x + all 8 weight matrices, fp32 -> fp16, one launch.
// x: 49152 blocks, then weights: 14336 blocks.
// ===================================================================
extern "C" __global__ void __launch_bounds__(256)
conv_all(const float* sx,
         const float* s0, const float* s1, const float* s2, const float* s3,
         const float* s4, const float* s5, const float* s6, const float* s7,
         __half* __restrict__ cvt)
{
    int b = blockIdx.x;
    const float* src; size_t doff; int lb;
    if      (b < 49152) { src = sx; doff = OFF_X;   lb = b; }
    else if (b < 50688) { src = s0; doff = OFF_EW1; lb = b - 49152; }
    else if (b < 52736) { src = s1; doff = OFF_EW2; lb = b - 50688; }
    else if (b < 53248) { src = s2; doff = OFF_MUW; lb = b - 52736; }
    else if (b < 53760) { src = s3; doff = OFF_LVW; lb = b - 53248; }
    else if (b < 54272) { src = s4; doff = OFF_DIW; lb = b - 53760; }
    else if (b < 56320) { src = s5; doff = OFF_DW1; lb = b - 54272; }
    else if (b < 60416) { src = s6; doff = OFF_DW2; lb = b - 56320; }
    else                { src = s7; doff = OFF_DW3; lb = b - 60416; }
    int idx = lb * 256 + threadIdx.x;
    ((__half2*)(cvt + doff))[idx] = __floats2half2_rn(src[idx * 2], src[idx * 2 + 1]);
}

// ===================================================================
// GEMM: C[B, Nt] = A[B, K] @ W[Nt, K]^T + bias
// CTA 128x128, 256 threads, 8 warps (2m x 4n), warp tile 64x32.
// 3-stage cp.async, 96KB smem -> 2 CTAs/SM, 16 warps/SM.
// mode bit0: lrelu; bit1: fp16 output (staged via smem); bit2: split fp32
//   output (Nt=512: cols<256 -> Cv/bias, else Cv2/bias2, stride 256).
// ===================================================================
extern "C" __global__ void __launch_bounds__(NTHREAD, 2)
gemm_h(const __half* __restrict__ A, const __half* __restrict__ W,
       const float* __restrict__ bias, const float* __restrict__ bias2,
       void* __restrict__ Cv, void* __restrict__ Cv2,
       int K, int Nt, int mode)
{
    extern __shared__ char smem[];
    const uint32_t sb = smem_u32(smem);
    const int tid = threadIdx.x;
    const int wid = tid >> 5;
    const int lid = tid & 31;
    const int g = lid >> 2;
    const int t = lid & 3;
    const int m0 = blockIdx.y * TM;
    const int n0 = blockIdx.x * TN;
    const int wm = (wid & 1) * 64;     // 2 m warp-positions
    const int wn = (wid >> 1) * 32;    // 4 n warp-positions

    // ldmatrix lane constants
    const int e    = lid & 7;
    const int bsel = (lid >> 3) & 1;
    const int hsel = lid >> 4;
    const uint32_t rowA = (uint32_t)(wm + e + bsel * 8) * 128;
    const uint32_t rowB = (uint32_t)(wn + e + bsel * 8) * 128;

    // cp.async mapping: 2048 16B chunks/stage; 8 per thread (4 A + 4 W row-grps)
    const int brow = tid >> 3, seg = tid & 7;      // brow 0..31
    const __half* srcA = A + (size_t)(m0 + brow) * K + seg * 8;
    const __half* srcW = W + (size_t)(n0 + brow) * K + seg * 8;
    const uint32_t dA = sb + brow * 128 + ((seg ^ (brow & 7)) * 16);
    const uint32_t dW = dA + AT_BYTES;
    const size_t rstep = (size_t)32 * K;           // 32 rows per sub-iteration

    const int KC = K >> 6;

    // prologue: fill 2 of 3 slots
#pragma unroll
    for (int s = 0; s < 2; s++) {
        const __half* pa = srcA + s * 64;
        const __half* pw = srcW + s * 64;
        uint32_t off = s * STG_BYTES;
#pragma unroll
        for (int i = 0; i < 4; i++) cp16(dA + off + i * 4096, pa + i * rstep);
#pragma unroll
        for (int i = 0; i < 4; i++) cp16(dW + off + i * 4096, pw + i * rstep);
        asm volatile("cp.async.commit_group;" ::: "memory");
    }

    float acc[4][4][4];
#pragma unroll
    for (int mf = 0; mf < 4; mf++)
#pragma unroll
        for (int nf = 0; nf < 4; nf++)
#pragma unroll
            for (int j = 0; j < 4; j++) acc[mf][nf][j] = 0.f;

    for (int kc = 0; kc < KC; kc++) {
        if (kc < KC - 1) asm volatile("cp.async.wait_group 1;" ::: "memory");
        else             asm volatile("cp.async.wait_group 0;" ::: "memory");
        __syncthreads();

        // refill: chunk kc+2 into slot (kc+2)%3 (its compute ended last iter)
        if (kc + 2 < KC) {
            int fs = (kc + 2) % 3;
            const __half* pa = srcA + (kc + 2) * 64;
            const __half* pw = srcW + (kc + 2) * 64;
            uint32_t off = fs * STG_BYTES;
#pragma unroll
            for (int i = 0; i < 4; i++) cp16(dA + off + i * 4096, pa + i * rstep);
#pragma unroll
            for (int i = 0; i < 4; i++) cp16(dW + off + i * 4096, pw + i * rstep);
            asm volatile("cp.async.commit_group;" ::: "memory");
        }

        const int slot = kc % 3;
        const uint32_t sAc = sb + slot * STG_BYTES;
        const uint32_t sWc = sAc + AT_BYTES;

#pragma unroll
        for (int j = 0; j < 4; j++) {
            const uint32_t so = (uint32_t)(((2 * j + hsel) ^ e) * 16);
            uint32_t af[4][4], bf[2][4];
#pragma unroll
            for (int mf = 0; mf < 4; mf++) ldm4(af[mf], sAc + rowA + mf * 2048 + so);
#pragma unroll
            for (int q = 0; q < 2; q++)  ldm4(bf[q], sWc + rowB + q * 2048 + so);
#pragma unroll
            for (int mf = 0; mf < 4; mf++)
#pragma unroll
                for (int q = 0; q < 2; q++) {
                    mma16(acc[mf][2 * q],     af[mf][0], af[mf][1], af[mf][2], af[mf][3],
                          bf[q][0], bf[q][2]);
                    mma16(acc[mf][2 * q + 1], af[mf][0], af[mf][1], af[mf][2], af[mf][3],
                          bf[q][1], bf[q][3]);
                }
        }
    }

    if (mode & 4) {
        // split fp32 output: Nt==512
#pragma unroll
        for (int nf = 0; nf < 4; nf++) {
            const int ng = n0 + wn + nf * 8 + t * 2;
            float* C = (ng < 256) ? (float*)Cv : (float*)Cv2;
            const float* bp = (ng < 256) ? bias : bias2;
            const int n = ng & 255;
            const float2 bn = *(const float2*)(bp + n);
#pragma unroll
            for (int mf = 0; mf < 4; mf++) {
                const int m = m0 + wm + mf * 16 + g;
                *(float2*)(C + (size_t)m * 256 + n) =
                    make_float2(acc[mf][nf][0] + bn.x, acc[mf][nf][1] + bn.y);
                *(float2*)(C + (size_t)(m + 8) * 256 + n) =
                    make_float2(acc[mf][nf][2] + bn.x, acc[mf][nf][3] + bn.y);
            }
        }
    } else if (!(mode & 2)) {
        float* C = (float*)Cv;
#pragma unroll
        for (int nf = 0; nf < 4; nf++) {
            const int n = n0 + wn + nf * 8 + t * 2;
            const float2 bn = *(const float2*)(bias + n);
#pragma unroll
            for (int mf = 0; mf < 4; mf++) {
                const int m = m0 + wm + mf * 16 + g;
                float v0 = acc[mf][nf][0] + bn.x;
                float v1 = acc[mf][nf][1] + bn.y;
                float v2 = acc[mf][nf][2] + bn.x;
                float v3 = acc[mf][nf][3] + bn.y;
                if (mode & 1) {
                    v0 = v0 >= 0.f ? v0 : 0.2f * v0;
                    v1 = v1 >= 0.f ? v1 : 0.2f * v1;
                    v2 = v2 >= 0.f ? v2 : 0.2f * v2;
                    v3 = v3 >= 0.f ? v3 : 0.2f * v3;
                }
                *(float2*)(C + (size_t)m * Nt + n)       = make_float2(v0, v1);
                *(float2*)(C + (size_t)(m + 8) * Nt + n) = make_float2(v2, v3);
            }
        }
    } else {
        // fp16 output staged through smem (stride 68 half2 rows, conflict-free)
        __half* C = (__half*)Cv;
        __syncthreads();
        __half2* se = (__half2*)smem;           // 128 rows x 68 half2 (34.8KB)
#pragma unroll
        for (int nf = 0; nf < 4; nf++) {
            const int n = wn + nf * 8 + t * 2;
            const float2 bn = *(const float2*)(bias + n0 + n);
#pragma unroll
            for (int mf = 0; mf < 4; mf++) {
                const int m = wm + mf * 16 + g;
                float v0 = acc[mf][nf][0] + bn.x;
                float v1 = acc[mf][nf][1] + bn.y;
                float v2 = acc[mf][nf][2] + bn.x;
                float v3 = acc[mf][nf][3] + bn.y;
                if (mode & 1) {
                    v0 = v0 >= 0.f ? v0 : 0.2f * v0;
                    v1 = v1 >= 0.f ? v1 : 0.2f * v1;
                    v2 = v2 >= 0.f ? v2 : 0.2f * v2;
                    v3 = v3 >= 0.f ? v3 : 0.2f * v3;
                }
                se[m * 68 + (n >> 1)]       = __floats2half2_rn(v0, v1);
                se[(m + 8) * 68 + (n >> 1)] = __floats2half2_rn(v2, v3);
            }
        }
        __syncthreads();
        // 128 rows x 16 uint4 per row = 2048 uint4; 8 iters x 256 threads
#pragma unroll
        for (int i = 0; i < 8; i++) {
            int lin = tid + i * NTHREAD;
            int row = lin >> 4, f8 = lin & 15;
            *(uint4*)(C + (size_t)(m0 + row) * Nt + n0 + f8 * 8) =
                *(const uint4*)((const __half2*)smem + row * 68 + f8 * 4);
        }
    }
}

// ===================================================================
// LayerNorm + leaky relu, warp-per-row, TWO-PASS (low regs, high occ).
// ===================================================================
extern "C" __global__ void __launch_bounds__(256)
ln_lrelu(const __half* __restrict__ X, __half* __restrict__ Y,
         const float* __restrict__ gw, const float* __restrict__ bw, int H)
{
    const int w = threadIdx.x >> 5, l = threadIdx.x & 31;
    const size_t r = (size_t)blockIdx.x * 8 + w;
    const uint4* x4 = (const uint4*)(X + r * H);
    uint4* y4 = (uint4*)(Y + r * H);
    const int V = H >> 8;

    float s = 0.f, s2 = 0.f;
    for (int i = 0; i < V; i++) {
        uint4 v = x4[l + (i << 5)];
        const __half2* h2 = (const __half2*)&v;
#pragma unroll
        for (int j = 0; j < 4; j++) {
            float2 f = __half22float2(h2[j]);
            s  += f.x + f.y;
            s2 += f.x * f.x + f.y * f.y;
        }
    }
#pragma unroll
    for (int o = 16; o; o >>= 1) {
        s  += __shfl_xor_sync(~0u, s,  o);
        s2 += __shfl_xor_sync(~0u, s2, o);
    }
    const float inv = 1.f / (float)H;
    const float mu = s * inv;
    const float var = s2 * inv - mu * mu;
    const float rs = rsqrtf(var + 1e-5f);

    for (int i = 0; i < V; i++) {
        uint4 v = x4[l + (i << 5)];
        const int c8 = (l + (i << 5)) * 2;
        const float4 g0 = ((const float4*)gw)[c8];
        const float4 g1 = ((const float4*)gw)[c8 + 1];
        const float4 b0 = ((const float4*)bw)[c8];
        const float4 b1 = ((const float4*)bw)[c8 + 1];
        const __half2* h2 = (const __half2*)&v;
        float2 f0 = __half22float2(h2[0]);
        float2 f1 = __half22float2(h2[1]);
        float2 f2 = __half22float2(h2[2]);
        float2 f3 = __half22float2(h2[3]);
        float o0 = (f0.x - mu) * rs * g0.x + b0.x;
        float o1 = (f0.y - mu) * rs * g0.y + b0.y;
        float o2 = (f1.x - mu) * rs * g0.z + b0.z;
        float o3 = (f1.y - mu) * rs * g0.w + b0.w;
        float o4 = (f2.x - mu) * rs * g1.x + b1.x;
        float o5 = (f2.y - mu) * rs * g1.y + b1.y;
        float o6 = (f3.x - mu) * rs * g1.z + b1.z;
        float o7 = (f3.y - mu) * rs * g1.w + b1.w;
        o0 = o0 >= 0.f ? o0 : 0.2f * o0;  o1 = o1 >= 0.f ? o1 : 0.2f * o1;
        o2 = o2 >= 0.f ? o2 : 0.2f * o2;  o3 = o3 >= 0.f ? o3 : 0.2f * o3;
        o4 = o4 >= 0.f ? o4 : 0.2f * o4;  o5 = o5 >= 0.f ? o5 : 0.2f * o5;
        o6 = o6 >= 0.f ? o6 : 0.2f * o6;  o7 = o7 >= 0.f ? o7 : 0.2f * o7;
        uint4 ov;
        __half2* oh = (__half2*)&ov;
        oh[0] = __floats2half2_rn(o0, o1);
        oh[1] = __floats2half2_rn(o2, o3);
        oh[2] = __floats2half2_rn(o4, o5);
        oh[3] = __floats2half2_rn(o6, o7);
        y4[l + (i << 5)] = ov;
    }
}

// ===================================================================
// Reparameterize + context-memory attention. One warp per row.
// ===================================================================
extern "C" __global__ void __launch_bounds__(256)
reparam_attn(const float* __restrict__ mu, const float* __restrict__ lv,
             const float* __restrict__ eps, const float* __restrict__ ctx,
             __half* __restrict__ zout)
{
    __shared__ float sctx[32 * 257];
    __shared__ float sz[8][256];
    __shared__ float sat[8][32];
    const int t = threadIdx.x, w = t >> 5, l = t & 31;
    for (int i = t; i < 32 * 256; i += 256) {
        int m = i >> 8, k = i & 255;
        sctx[m * 257 + k] = ctx[i];
    }
    __syncthreads();
    const size_t r = (size_t)blockIdx.x * 8 + w;
    const float* murow = mu + r * 256;
    const float* lvrow = lv + r * 256;
    const float* erow  = eps + r * 256;
    float z[8];
#pragma unroll
    for (int j = 0; j < 4; j++) {
        int k = j * 64 + 2 * l;
        z[j * 2]     = murow[k]     + erow[k]     * expf(0.5f * lvrow[k]);
        z[j * 2 + 1] = murow[k + 1] + erow[k + 1] * expf(0.5f * lvrow[k + 1]);
        sz[w][k] = z[j * 2];
        sz[w][k + 1] = z[j * 2 + 1];
    }
    __syncwarp();
    float dot = 0.f;
    const float* cm = &sctx[l * 257];
#pragma unroll 8
    for (int k = 0; k < 256; k++) dot += sz[w][k] * cm[k];
    float mx = dot;
#pragma unroll
    for (int o = 16; o; o >>= 1) mx = fmaxf(mx, __shfl_xor_sync(~0u, mx, o));
    float e = expf(dot - mx);
    float sum = e;
#pragma unroll
    for (int o = 16; o; o >>= 1) sum += __shfl_xor_sync(~0u, sum, o);
    sat[w][l] = e / sum;
    __syncwarp();
    __half2* zo = (__half2*)(zout + r * 256);
#pragma unroll
    for (int j = 0; j < 4; j++) {
        int k = j * 64 + 2 * l;
        float a0 = 0.f, a1 = 0.f;
#pragma unroll
        for (int m = 0; m < 32; m++) {
            a0 += sat[w][m] * sctx[m * 257 + k];
            a1 += sat[w][m] * sctx[m * 257 + k + 1];
        }
        zo[k >> 1] = __floats2half2_rn(z[j * 2] + 0.1f * a0, z[j * 2 + 1] + 0.1f * a1);
    }
}

// ===================================================================
extern "C" void kernel_launch(void* const* d_in, const int* in_sizes, int n_in,
                              void* d_out, int out_size)
{
    (void)in_sizes; (void)n_in; (void)out_size;
    const float* x      = (const float*)d_in[0];
    const float* eps    = (const float*)d_in[1];
    const float* enc_w1 = (const float*)d_in[2];
    const float* enc_b1 = (const float*)d_in[3];
    const float* ln1_g  = (const float*)d_in[4];
    const float* ln1_b  = (const float*)d_in[5];
    const float* enc_w2 = (const float*)d_in[6];
    const float* enc_b2 = (const float*)d_in[7];
    const float* ln2_g  = (const float*)d_in[8];
    const float* ln2_b  = (const float*)d_in[9];
    const float* mu_w   = (const float*)d_in[10];
    const float* mu_b   = (const float*)d_in[11];
    const float* lv_w   = (const float*)d_in[12];
    const float* lv_b   = (const float*)d_in[13];
    const float* di_w   = (const float*)d_in[14];
    const float* di_b   = (const float*)d_in[15];
    const float* dec_w1 = (const float*)d_in[16];
    const float* dec_b1 = (const float*)d_in[17];
    const float* dln1_g = (const float*)d_in[18];
    const float* dln1_b = (const float*)d_in[19];
    const float* dec_w2 = (const float*)d_in[20];
    const float* dec_b2 = (const float*)d_in[21];
    const float* dln2_g = (const float*)d_in[22];
    const float* dln2_b = (const float*)d_in[23];
    const float* dec_w3 = (const float*)d_in[24];
    const float* dec_b3 = (const float*)d_in[25];
    const float* ctx    = (const float*)d_in[26];

    float* out    = (float*)d_out;
    float* out_mu = out + (size_t)B_ * D_;
    float* out_lv = out_mu + (size_t)B_ * L_;

    float* f32buf = nullptr; __half* hB = nullptr; __half* h1 = nullptr; __half* cvt = nullptr;
    cudaGetSymbolAddress((void**)&f32buf, g_f32);
    cudaGetSymbolAddress((void**)&hB, g_h0);
    cudaGetSymbolAddress((void**)&h1, g_h1);
    cudaGetSymbolAddress((void**)&cvt, g_cvt);
    __half* hA = (__half*)f32buf;

    cudaFuncSetAttribute(gemm_h, cudaFuncAttributeMaxDynamicSharedMemorySize, SM_TOTAL);

    conv_all<<<63488, 256>>>(x, enc_w1, enc_w2, mu_w, lv_w, di_w, dec_w1, dec_w2, dec_w3, cvt);

    const dim3 blk(NTHREAD);
    const dim3 gH(H_ / TN, B_ / TM);        // (8, 256)
    const dim3 gML(512 / TN, B_ / TM);      // (4, 256) merged mu+lv
    const dim3 g2H(2 * H_ / TN, B_ / TM);   // (16, 256)
    const dim3 gD(D_ / TN, B_ / TM);        // (6, 256)

    // encoder
    gemm_h<<<gH, blk, SM_TOTAL>>>(cvt + OFF_X, cvt + OFF_EW1, enc_b1, nullptr,
                                  hA, nullptr, D_, H_, 2);
    ln_lrelu<<<B_ / 8, 256>>>(hA, hB, ln1_g, ln1_b, H_);
    gemm_h<<<gH, blk, SM_TOTAL>>>(hB, cvt + OFF_EW2, enc_b2, nullptr,
                                  hA, nullptr, H_, H_, 2);
    ln_lrelu<<<B_ / 8, 256>>>(hA, hB, ln2_g, ln2_b, H_);
    // merged mu + logvar (weights contiguous at OFF_MUW)
    gemm_h<<<gML, blk, SM_TOTAL>>>(hB, cvt + OFF_MUW, mu_b, lv_b,
                                   out_mu, out_lv, H_, 512, 4);
    // reparameterize + context attention
    reparam_attn<<<B_ / 8, 256>>>(out_mu, out_lv, eps, ctx, h1);
    // decoder
    gemm_h<<<gH, blk, SM_TOTAL>>>(h1, cvt + OFF_DIW, di_b, nullptr,
                                  hA, nullptr, L_, H_, 3);
    gemm_h<<<gH, blk, SM_TOTAL>>>(hA, cvt + OFF_DW1, dec_b1, nullptr,
                                  hB, nullptr, H_, H_, 2);
    ln_lrelu<<<B_ / 8, 256>>>(hB, hA, dln1_g, dln1_b, H_);
    gemm_h<<<g2H, blk, SM_TOTAL>>>(hA, cvt + OFF_DW2, dec_b2, nullptr,
                                   hB, nullptr, H_, 2 * H_, 2);
    ln_lrelu<<<B_ / 8, 256>>>(hB, hA, dln2_g, dln2_b, 2 * H_);
    gemm_h<<<gD, blk, SM_TOTAL>>>(hA, cvt + OFF_DW3, dec_b3, nullptr,
                                  out, nullptr, 2 * H_, D_, 0);
}

// round 17
// speedup vs baseline: 1.0151x; 1.0151x over previous
#include <cuda_runtime.h>
#include <cuda_fp16.h>
#include <cstdint>

#define B_ 32768
#define D_ 768
#define H_ 1024
#define L_ 256

// ---------------- GEMM tiling ----------------
#define TM 128
#define TN 128
#define NTHREAD 128
#define AT_BYTES (128 * 128)              // A tile: 128 rows x 128B
#define WT_BYTES (128 * 128)              // W tile: 128 rows x 128B
#define STG_BYTES (AT_BYTES + WT_BYTES)   // 32768
#define NSTAGE 3
#define SM_TOTAL (NSTAGE * STG_BYTES)     // 98304 -> 2 CTAs/SM

// ---------------- scratch ----------------
static __device__ float  g_f32[(size_t)B_ * 2048];   // aliased as half buffer A
static __device__ __half g_h0[(size_t)B_ * 2048];    // half buffer B
static __device__ __half g_h1[(size_t)B_ * 256];     // z_enh
static __device__ __half g_cvt[32505856];            // x + weights, fp16
static __device__ float  g_stats[(size_t)B_ * 64];   // per-row LN partials

// offsets into g_cvt (halfs)
#define OFF_X    0
#define OFF_EW1  25165824
#define OFF_EW2  25952256
#define OFF_MUW  27000832
#define OFF_LVW  27262976
#define OFF_DIW  27525120
#define OFF_DW1  27787264
#define OFF_DW2  28835840
#define OFF_DW3  30932992

// ---------------- helpers ----------------
__device__ __forceinline__ uint32_t smem_u32(const void* p) {
    uint32_t a;
    asm("{ .reg .u64 t; cvta.to.shared.u64 t, %1; cvt.u32.u64 %0, t; }" : "=r"(a) : "l"(p));
    return a;
}
__device__ __forceinline__ void cp16(uint32_t sa, const void* g) {
    asm volatile("cp.async.cg.shared.global [%0], [%1], 16;" :: "r"(sa), "l"(g));
}
__device__ __forceinline__ void mma16(float* c, uint32_t a0, uint32_t a1, uint32_t a2, uint32_t a3,
                                      uint32_t b0, uint32_t b1) {
    asm volatile("mma.sync.aligned.m16n8k16.row.col.f32.f16.f16.f32 "
                 "{%0,%1,%2,%3}, {%4,%5,%6,%7}, {%8,%9}, {%0,%1,%2,%3};"
                 : "+f"(c[0]), "+f"(c[1]), "+f"(c[2]), "+f"(c[3])
                 : "r"(a0), "r"(a1), "r"(a2), "r"(a3), "r"(b0), "r"(b1));
}
__device__ __forceinline__ void ldm4(uint32_t* r, uint32_t addr) {
    asm volatile("ldmatrix.sync.aligned.m8n8.x4.shared.b16 {%0,%1,%2,%3}, [%4];"
                 : "=r"(r[0]), "=r"(r[1]), "=r"(r[2]), "=r"(r[3]) : "r"(addr));
}

// ===================================================================
// conv_all: x + all 8 weight matrices, fp32 -> fp16, one launch.
// ===================================================================
extern "C" __global__ void __launch_bounds__(256)
conv_all(const float* sx,
         const float* s0, const float* s1, const float* s2, const float* s3,
         const float* s4, const float* s5, const float* s6, const float* s7,
         __half* __restrict__ cvt)
{
    int b = blockIdx.x;
    const float* src; size_t doff; int lb;
    if      (b < 49152) { src = sx; doff = OFF_X;   lb = b; }
    else if (b < 50688) { src = s0; doff = OFF_EW1; lb = b - 49152; }
    else if (b < 52736) { src = s1; doff = OFF_EW2; lb = b - 50688; }
    else if (b < 53248) { src = s2; doff = OFF_MUW; lb = b - 52736; }
    else if (b < 53760) { src = s3; doff = OFF_LVW; lb = b - 53248; }
    else if (b < 54272) { src = s4; doff = OFF_DIW; lb = b - 53760; }
    else if (b < 56320) { src = s5; doff = OFF_DW1; lb = b - 54272; }
    else if (b < 60416) { src = s6; doff = OFF_DW2; lb = b - 56320; }
    else                { src = s7; doff = OFF_DW3; lb = b - 60416; }
    int idx = lb * 256 + threadIdx.x;
    ((__half2*)(cvt + doff))[idx] = __floats2half2_rn(src[idx * 2], src[idx * 2 + 1]);
}

// ===================================================================
// GEMM: C[B, Nt] = A[B, K] @ W[Nt, K]^T + bias
// CTA 128x128, 128 threads, 4 warps (2m x 2n), warp tile 64x64.
// 3-stage cp.async, 96KB smem -> 2 CTAs/SM. ldmatrix fragment loads.
// mode bit0: lrelu; bit1: fp16 output (staged via smem); bit2: split fp32
//   (Nt=512 merged mu/lv); bit3: emit per-row LN partial stats.
// ===================================================================
extern "C" __global__ void __launch_bounds__(NTHREAD, 2)
gemm_h(const __half* __restrict__ A, const __half* __restrict__ W,
       const float* __restrict__ bias, const float* __restrict__ bias2,
       void* __restrict__ Cv, void* __restrict__ Cv2,
       float* __restrict__ stats,
       int K, int Nt, int mode)
{
    extern __shared__ char smem[];
    const uint32_t sb = smem_u32(smem);
    const int tid = threadIdx.x;
    const int wid = tid >> 5;
    const int lid = tid & 31;
    const int g = lid >> 2;
    const int t = lid & 3;
    const int m0 = blockIdx.y * TM;
    const int n0 = blockIdx.x * TN;
    const int wm = (wid & 1) * 64;     // 2 m warp-positions
    const int wn = (wid >> 1) * 64;    // 2 n warp-positions

    // ldmatrix lane constants
    const int e    = lid & 7;
    const int bsel = (lid >> 3) & 1;
    const int hsel = lid >> 4;
    const uint32_t rowA = (uint32_t)(wm + e + bsel * 8) * 128;
    const uint32_t rowB = (uint32_t)(wn + e + bsel * 8) * 128;

    // cp.async mapping: 2048 16B chunks/stage; 16 per thread (8 A + 8 W rows)
    const int brow = tid >> 3, seg = tid & 7;      // brow 0..15
    const __half* srcA = A + (size_t)(m0 + brow) * K + seg * 8;
    const __half* srcW = W + (size_t)(n0 + brow) * K + seg * 8;
    const uint32_t dA = sb + brow * 128 + ((seg ^ (brow & 7)) * 16);
    const uint32_t dW = dA + AT_BYTES;
    const size_t rstep = (size_t)16 * K;

    const int KC = K >> 6;

    // prologue: fill 2 of 3 slots
#pragma unroll
    for (int s = 0; s < 2; s++) {
        const __half* pa = srcA + s * 64;
        const __half* pw = srcW + s * 64;
        uint32_t off = s * STG_BYTES;
#pragma unroll
        for (int i = 0; i < 8; i++) cp16(dA + off + i * 2048, pa + i * rstep);
#pragma unroll
        for (int i = 0; i < 8; i++) cp16(dW + off + i * 2048, pw + i * rstep);
        asm volatile("cp.async.commit_group;" ::: "memory");
    }

    float acc[4][8][4];
#pragma unroll
    for (int mf = 0; mf < 4; mf++)
#pragma unroll
        for (int nf = 0; nf < 8; nf++)
#pragma unroll
            for (int j = 0; j < 4; j++) acc[mf][nf][j] = 0.f;

    for (int kc = 0; kc < KC; kc++) {
        if (kc < KC - 1) asm volatile("cp.async.wait_group 1;" ::: "memory");
        else             asm volatile("cp.async.wait_group 0;" ::: "memory");
        __syncthreads();

        // refill: chunk kc+2 into slot (kc+2)%3 (its compute ended last iter)
        if (kc + 2 < KC) {
            int fs = (kc + 2) % 3;
            const __half* pa = srcA + (kc + 2) * 64;
            const __half* pw = srcW + (kc + 2) * 64;
            uint32_t off = fs * STG_BYTES;
#pragma unroll
            for (int i = 0; i < 8; i++) cp16(dA + off + i * 2048, pa + i * rstep);
#pragma unroll
            for (int i = 0; i < 8; i++) cp16(dW + off + i * 2048, pw + i * rstep);
            asm volatile("cp.async.commit_group;" ::: "memory");
        }

        const int slot = kc % 3;
        const uint32_t sAc = sb + slot * STG_BYTES;
        const uint32_t sWc = sAc + AT_BYTES;

        // double-buffered fragments over 4 k16-steps
        uint32_t af[2][4][4], bf[2][4][4];
        {
            const uint32_t so = (uint32_t)((hsel ^ e) * 16);
#pragma unroll
            for (int mf = 0; mf < 4; mf++) ldm4(af[0][mf], sAc + rowA + mf * 2048 + so);
#pragma unroll
            for (int q = 0; q < 4; q++)  ldm4(bf[0][q], sWc + rowB + q * 2048 + so);
        }
#pragma unroll
        for (int j = 0; j < 4; j++) {
            const int cur = j & 1, nxt = cur ^ 1;
            if (j < 3) {
                const uint32_t so = (uint32_t)(((2 * (j + 1) + hsel) ^ e) * 16);
#pragma unroll
                for (int mf = 0; mf < 4; mf++) ldm4(af[nxt][mf], sAc + rowA + mf * 2048 + so);
#pragma unroll
                for (int q = 0; q < 4; q++)  ldm4(bf[nxt][q], sWc + rowB + q * 2048 + so);
            }
#pragma unroll
            for (int mf = 0; mf < 4; mf++)
#pragma unroll
                for (int q = 0; q < 4; q++) {
                    mma16(acc[mf][2 * q],     af[cur][mf][0], af[cur][mf][1],
                          af[cur][mf][2], af[cur][mf][3], bf[cur][q][0], bf[cur][q][2]);
                    mma16(acc[mf][2 * q + 1], af[cur][mf][0], af[cur][mf][1],
                          af[cur][mf][2], af[cur][mf][3], bf[cur][q][1], bf[cur][q][3]);
                }
        }
    }

    // ---- LN partial stats (pre-LN layers): sum/sumsq over this warp's 64 cols ----
    if (mode & 8) {
        const int slot = blockIdx.x * 2 + (wid >> 1);
#pragma unroll
        for (int mf = 0; mf < 4; mf++)
#pragma unroll
            for (int half = 0; half < 2; half++) {
                float s = 0.f, s2 = 0.f;
#pragma unroll
                for (int nf = 0; nf < 8; nf++) {
                    const int n = n0 + wn + nf * 8 + t * 2;
                    float va = acc[mf][nf][half * 2]     + bias[n];
                    float vb = acc[mf][nf][half * 2 + 1] + bias[n + 1];
                    s += va + vb;
                    s2 += va * va + vb * vb;
                }
                s  += __shfl_xor_sync(~0u, s, 1);  s2 += __shfl_xor_sync(~0u, s2, 1);
                s  += __shfl_xor_sync(~0u, s, 2);  s2 += __shfl_xor_sync(~0u, s2, 2);
                if (t == 0) {
                    const size_t row = (size_t)(m0 + wm + mf * 16 + g + half * 8);
                    stats[row * 64 + slot]      = s;
                    stats[row * 64 + 32 + slot] = s2;
                }
            }
    }

    if (mode & 4) {
        // split fp32 output: Nt==512
#pragma unroll
        for (int nf = 0; nf < 8; nf++) {
            const int ng = n0 + wn + nf * 8 + t * 2;
            float* C = (ng < 256) ? (float*)Cv : (float*)Cv2;
            const float* bp = (ng < 256) ? bias : bias2;
            const int n = ng & 255;
            const float2 bn = *(const float2*)(bp + n);
#pragma unroll
            for (int mf = 0; mf < 4; mf++) {
                const int m = m0 + wm + mf * 16 + g;
                *(float2*)(C + (size_t)m * 256 + n) =
                    make_float2(acc[mf][nf][0] + bn.x, acc[mf][nf][1] + bn.y);
                *(float2*)(C + (size_t)(m + 8) * 256 + n) =
                    make_float2(acc[mf][nf][2] + bn.x, acc[mf][nf][3] + bn.y);
            }
        }
    } else if (!(mode & 2)) {
        float* C = (float*)Cv;
#pragma unroll
        for (int nf = 0; nf < 8; nf++) {
            const int n = n0 + wn + nf * 8 + t * 2;
            const float2 bn = *(const float2*)(bias + n);
#pragma unroll
            for (int mf = 0; mf < 4; mf++) {
                const int m = m0 + wm + mf * 16 + g;
                float v0 = acc[mf][nf][0] + bn.x;
                float v1 = acc[mf][nf][1] + bn.y;
                float v2 = acc[mf][nf][2] + bn.x;
                float v3 = acc[mf][nf][3] + bn.y;
                if (mode & 1) {
                    v0 = v0 >= 0.f ? v0 : 0.2f * v0;
                    v1 = v1 >= 0.f ? v1 : 0.2f * v1;
                    v2 = v2 >= 0.f ? v2 : 0.2f * v2;
                    v3 = v3 >= 0.f ? v3 : 0.2f * v3;
                }
                *(float2*)(C + (size_t)m * Nt + n)       = make_float2(v0, v1);
                *(float2*)(C + (size_t)(m + 8) * Nt + n) = make_float2(v2, v3);
            }
        }
    } else {
        // fp16 output staged through smem (stride 68 half2 rows, conflict-free)
        __half* C = (__half*)Cv;
        __syncthreads();
        __half2* se = (__half2*)smem;           // 128 rows x 68 half2 (34.8KB)
#pragma unroll
        for (int nf = 0; nf < 8; nf++) {
            const int n = wn + nf * 8 + t * 2;
            const float2 bn = *(const float2*)(bias + n0 + n);
#pragma unroll
            for (int mf = 0; mf < 4; mf++) {
                const int m = wm + mf * 16 + g;
                float v0 = acc[mf][nf][0] + bn.x;
                float v1 = acc[mf][nf][1] + bn.y;
                float v2 = acc[mf][nf][2] + bn.x;
                float v3 = acc[mf][nf][3] + bn.y;
                if (mode & 1) {
                    v0 = v0 >= 0.f ? v0 : 0.2f * v0;
                    v1 = v1 >= 0.f ? v1 : 0.2f * v1;
                    v2 = v2 >= 0.f ? v2 : 0.2f * v2;
                    v3 = v3 >= 0.f ? v3 : 0.2f * v3;
                }
                se[m * 68 + (n >> 1)]       = __floats2half2_rn(v0, v1);
                se[(m + 8) * 68 + (n >> 1)] = __floats2half2_rn(v2, v3);
            }
        }
        __syncthreads();
        // 128 rows x 16 uint4 per row = 2048 uint4; 16 iters x 128 threads
#pragma unroll
        for (int i = 0; i < 16; i++) {
            int lin = tid + i * NTHREAD;
            int row = lin >> 4, f8 = lin & 15;
            *(uint4*)(C + (size_t)(m0 + row) * Nt + n0 + f8 * 8) =
                *(const uint4*)((const __half2*)smem + row * 68 + f8 * 4);
        }
    }
}

// ===================================================================
// LayerNorm + leaky relu, warp-per-row, SINGLE-PASS: stats come
// precomputed from the GEMM epilogue (stats[row*64 + slot]).
// ===================================================================
extern "C" __global__ void __launch_bounds__(256)
ln_lrelu(const __half* __restrict__ X, __half* __restrict__ Y,
         const float* __restrict__ gw, const float* __restrict__ bw,
         const float* __restrict__ stats, int H)
{
    const int w = threadIdx.x >> 5, l = threadIdx.x & 31;
    const size_t r = (size_t)blockIdx.x * 8 + w;
    const uint4* x4 = (const uint4*)(X + r * H);
    uint4* y4 = (uint4*)(Y + r * H);
    const int V = H >> 8;
    const int nslots = H >> 6;     // 16 (H=1024) or 32 (H=2048)

    float s = 0.f, s2 = 0.f;
    if (l < nslots) {
        s  = stats[r * 64 + l];
        s2 = stats[r * 64 + 32 + l];
    }
#pragma unroll
    for (int o = 16; o; o >>= 1) {
        s  += __shfl_xor_sync(~0u, s,  o);
        s2 += __shfl_xor_sync(~0u, s2, o);
    }
    const float inv = 1.f / (float)H;
    const float mu = s * inv;
    const float var = s2 * inv - mu * mu;
    const float rs = rsqrtf(var + 1e-5f);

    for (int i = 0; i < V; i++) {
        uint4 v = x4[l + (i << 5)];
        const int c8 = (l + (i << 5)) * 2;
        const float4 g0 = ((const float4*)gw)[c8];
        const float4 g1 = ((const float4*)gw)[c8 + 1];
        const float4 b0 = ((const float4*)bw)[c8];
        const float4 b1 = ((const float4*)bw)[c8 + 1];
        const __half2* h2 = (const __half2*)&v;
        float2 f0 = __half22float2(h2[0]);
        float2 f1 = __half22float2(h2[1]);
        float2 f2 = __half22float2(h2[2]);
        float2 f3 = __half22float2(h2[3]);
        float o0 = (f0.x - mu) * rs * g0.x + b0.x;
        float o1 = (f0.y - mu) * rs * g0.y + b0.y;
        float o2 = (f1.x - mu) * rs * g0.z + b0.z;
        float o3 = (f1.y - mu) * rs * g0.w + b0.w;
        float o4 = (f2.x - mu) * rs * g1.x + b1.x;
        float o5 = (f2.y - mu) * rs * g1.y + b1.y;
        float o6 = (f3.x - mu) * rs * g1.z + b1.z;
        float o7 = (f3.y - mu) * rs * g1.w + b1.w;
        o0 = o0 >= 0.f ? o0 : 0.2f * o0;  o1 = o1 >= 0.f ? o1 : 0.2f * o1;
        o2 = o2 >= 0.f ? o2 : 0.2f * o2;  o3 = o3 >= 0.f ? o3 : 0.2f * o3;
        o4 = o4 >= 0.f ? o4 : 0.2f * o4;  o5 = o5 >= 0.f ? o5 : 0.2f * o5;
        o6 = o6 >= 0.f ? o6 : 0.2f * o6;  o7 = o7 >= 0.f ? o7 : 0.2f * o7;
        uint4 ov;
        __half2* oh = (__half2*)&ov;
        oh[0] = __floats2half2_rn(o0, o1);
        oh[1] = __floats2half2_rn(o2, o3);
        oh[2] = __floats2half2_rn(o4, o5);
        oh[3] = __floats2half2_rn(o6, o7);
        y4[l + (i << 5)] = ov;
    }
}

// ===================================================================
// Reparameterize + context-memory attention. One warp per row.
// ===================================================================
extern "C" __global__ void __launch_bounds__(256)
reparam_attn(const float* __restrict__ mu, const float* __restrict__ lv,
             const float* __restrict__ eps, const float* __restrict__ ctx,
             __half* __restrict__ zout)
{
    __shared__ float sctx[32 * 257];
    __shared__ float sz[8][256];
    __shared__ float sat[8][32];
    const int t = threadIdx.x, w = t >> 5, l = t & 31;
    for (int i = t; i < 32 * 256; i += 256) {
        int m = i >> 8, k = i & 255;
        sctx[m * 257 + k] = ctx[i];
    }
    __syncthreads();
    const size_t r = (size_t)blockIdx.x * 8 + w;
    const float* murow = mu + r * 256;
    const float* lvrow = lv + r * 256;
    const float* erow  = eps + r * 256;
    float z[8];
#pragma unroll
    for (int j = 0; j < 4; j++) {
        int k = j * 64 + 2 * l;
        z[j * 2]     = murow[k]     + erow[k]     * expf(0.5f * lvrow[k]);
        z[j * 2 + 1] = murow[k + 1] + erow[k + 1] * expf(0.5f * lvrow[k + 1]);
        sz[w][k] = z[j * 2];
        sz[w][k + 1] = z[j * 2 + 1];
    }
    __syncwarp();
    float dot = 0.f;
    const float* cm = &sctx[l * 257];
#pragma unroll 8
    for (int k = 0; k < 256; k++) dot += sz[w][k] * cm[k];
    float mx = dot;
#pragma unroll
    for (int o = 16; o; o >>= 1) mx = fmaxf(mx, __shfl_xor_sync(~0u, mx, o));
    float e = expf(dot - mx);
    float sum = e;
#pragma unroll
    for (int o = 16; o; o >>= 1) sum += __shfl_xor_sync(~0u, sum, o);
    sat[w][l] = e / sum;
    __syncwarp();
    __half2* zo = (__half2*)(zout + r * 256);
#pragma unroll
    for (int j = 0; j < 4; j++) {
        int k = j * 64 + 2 * l;
        float a0 = 0.f, a1 = 0.f;
#pragma unroll
        for (int m = 0; m < 32; m++) {
            a0 += sat[w][m] * sctx[m * 257 + k];
            a1 += sat[w][m] * sctx[m * 257 + k + 1];
        }
        zo[k >> 1] = __floats2half2_rn(z[j * 2] + 0.1f * a0, z[j * 2 + 1] + 0.1f * a1);
    }
}

// ===================================================================
extern "C" void kernel_launch(void* const* d_in, const int* in_sizes, int n_in,
                              void* d_out, int out_size)
{
    (void)in_sizes; (void)n_in; (void)out_size;
    const float* x      = (const float*)d_in[0];
    const float* eps    = (const float*)d_in[1];
    const float* enc_w1 = (const float*)d_in[2];
    const float* enc_b1 = (const float*)d_in[3];
    const float* ln1_g  = (const float*)d_in[4];
    const float* ln1_b  = (const float*)d_in[5];
    const float* enc_w2 = (const float*)d_in[6];
    const float* enc_b2 = (const float*)d_in[7];
    const float* ln2_g  = (const float*)d_in[8];
    const float* ln2_b  = (const float*)d_in[9];
    const float* mu_w   = (const float*)d_in[10];
    const float* mu_b   = (const float*)d_in[11];
    const float* lv_w   = (const float*)d_in[12];
    const float* lv_b   = (const float*)d_in[13];
    const float* di_w   = (const float*)d_in[14];
    const float* di_b   = (const float*)d_in[15];
    const float* dec_w1 = (const float*)d_in[16];
    const float* dec_b1 = (const float*)d_in[17];
    const float* dln1_g = (const float*)d_in[18];
    const float* dln1_b = (const float*)d_in[19];
    const float* dec_w2 = (const float*)d_in[20];
    const float* dec_b2 = (const float*)d_in[21];
    const float* dln2_g = (const float*)d_in[22];
    const float* dln2_b = (const float*)d_in[23];
    const float* dec_w3 = (const float*)d_in[24];
    const float* dec_b3 = (const float*)d_in[25];
    const float* ctx    = (const float*)d_in[26];

    float* out    = (float*)d_out;
    float* out_mu = out + (size_t)B_ * D_;
    float* out_lv = out_mu + (size_t)B_ * L_;

    float* f32buf = nullptr; __half* hB = nullptr; __half* h1 = nullptr;
    __half* cvt = nullptr; float* stats = nullptr;
    cudaGetSymbolAddress((void**)&f32buf, g_f32);
    cudaGetSymbolAddress((void**)&hB, g_h0);
    cudaGetSymbolAddress((void**)&h1, g_h1);
    cudaGetSymbolAddress((void**)&cvt, g_cvt);
    cudaGetSymbolAddress((void**)&stats, g_stats);
    __half* hA = (__half*)f32buf;

    cudaFuncSetAttribute(gemm_h, cudaFuncAttributeMaxDynamicSharedMemorySize, SM_TOTAL);

    conv_all<<<63488, 256>>>(x, enc_w1, enc_w2, mu_w, lv_w, di_w, dec_w1, dec_w2, dec_w3, cvt);

    const dim3 blk(NTHREAD);
    const dim3 gH(H_ / TN, B_ / TM);        // (8, 256)
    const dim3 gML(512 / TN, B_ / TM);      // (4, 256) merged mu+lv
    const dim3 g2H(2 * H_ / TN, B_ / TM);   // (16, 256)
    const dim3 gD(D_ / TN, B_ / TM);        // (6, 256)

    // encoder
    gemm_h<<<gH, blk, SM_TOTAL>>>(cvt + OFF_X, cvt + OFF_EW1, enc_b1, nullptr,
                                  hA, nullptr, stats, D_, H_, 10);
    ln_lrelu<<<B_ / 8, 256>>>(hA, hB, ln1_g, ln1_b, stats, H_);
    gemm_h<<<gH, blk, SM_TOTAL>>>(hB, cvt + OFF_EW2, enc_b2, nullptr,
                                  hA, nullptr, stats, H_, H_, 10);
    ln_lrelu<<<B_ / 8, 256>>>(hA, hB, ln2_g, ln2_b, stats, H_);
    // merged mu + logvar (weights contiguous at OFF_MUW)
    gemm_h<<<gML, blk, SM_TOTAL>>>(hB, cvt + OFF_MUW, mu_b, lv_b,
                                   out_mu, out_lv, nullptr, H_, 512, 4);
    // reparameterize + context attention
    reparam_attn<<<B_ / 8, 256>>>(out_mu, out_lv, eps, ctx, h1);
    // decoder
    gemm_h<<<gH, blk, SM_TOTAL>>>(h1, cvt + OFF_DIW, di_b, nullptr,
                                  hA, nullptr, nullptr, L_, H_, 3);
    gemm_h<<<gH, blk, SM_TOTAL>>>(hA, cvt + OFF_DW1, dec_b1, nullptr,
                                  hB, nullptr, stats, H_, H_, 10);
    ln_lrelu<<<B_ / 8, 256>>>(hB, hA, dln1_g, dln1_b, stats, H_);
    gemm_h<<<g2H, blk, SM_TOTAL>>>(hA, cvt + OFF_DW2, dec_b2, nullptr,
                                   hB, nullptr, stats, H_, 2 * H_, 10);
    ln_lrelu<<<B_ / 8, 256>>>(hB, hA, dln2_g, dln2_b, stats, 2 * H_);
    gemm_h<<<gD, blk, SM_TOTAL>>>(hA, cvt + OFF_DW3, dec_b3, nullptr,
                                  out, nullptr, nullptr, 2 * H_, D_, 0);
}